// round 3
// baseline (speedup 1.0000x reference)
#include <cuda_runtime.h>
#include <math.h>

#define KM 16
#define DM 16

__device__ float g_M[KM][DM][DM];   // M = L^{-1}, lower triangular (zeros above diag)
__device__ float g_v[KM][DM];       // v = M @ mu
__device__ float g_c[KM];           // Phi / sqrt(2*pi*det(Sigma))

// ---------------------------------------------------------------------------
// Precompute: 1 block x 512 threads = 16 warps, one warp per mixture.
// Only cheap __syncwarp barriers; mixtures fully independent.
// ---------------------------------------------------------------------------
__global__ void gmm_precompute(const float* __restrict__ Phi,
                               const float* __restrict__ mu,
                               const float* __restrict__ Sigma) {
    __shared__ float L[KM][DM][DM + 1];
    __shared__ float Mi[KM][DM][DM + 1];

    int k    = threadIdx.x >> 5;          // warp = mixture
    int lane = threadIdx.x & 31;
    int r    = lane & 15;
    bool act = lane < 16;

    if (act)
        for (int j = 0; j < DM; j++)
            L[k][r][j] = Sigma[(k * DM + r) * DM + j];
    __syncwarp();

    // Left-looking Cholesky
    for (int p = 0; p < DM; p++) {
        if (act && r == p) {
            float s = L[k][p][p];
            for (int q = 0; q < p; q++) s -= L[k][p][q] * L[k][p][q];
            L[k][p][p] = sqrtf(s);
        }
        __syncwarp();
        if (act && r > p) {
            float s = L[k][r][p];
            for (int q = 0; q < p; q++) s -= L[k][r][q] * L[k][p][q];
            L[k][r][p] = s / L[k][p][p];
        }
        __syncwarp();
    }

    // Mi = L^{-1}: lane r computes column r
    if (act) {
        int c = r;
        for (int i = 0; i < c; i++) Mi[k][i][c] = 0.0f;
        Mi[k][c][c] = 1.0f / L[k][c][c];
        for (int i = c + 1; i < DM; i++) {
            float s = 0.0f;
            for (int q = c; q < i; q++) s += L[k][i][q] * Mi[k][q][c];
            Mi[k][i][c] = -s / L[k][i][i];
        }
    }
    __syncwarp();

    if (act) {
        float v = 0.0f;
        for (int j = 0; j <= r; j++) v += Mi[k][r][j] * mu[k * DM + j];
        g_v[k][r] = v;
        for (int j = 0; j < DM; j++) g_M[k][r][j] = Mi[k][r][j];
        if (r == 0) {
            float prod = 1.0f;
            for (int i = 0; i < DM; i++) prod *= L[k][i][i];   // sqrt(det)
            g_c[k] = Phi[k] / (sqrtf(2.0f * 3.14159265358979323846f) * prod);
        }
    }
}

// ---------------------------------------------------------------------------
// Main kernel: 2 samples per thread as one packed f32x2 stream.
// 64-reg budget -> 4 blocks/SM -> occ 50%.
// ---------------------------------------------------------------------------
typedef unsigned long long u64;

__device__ __forceinline__ u64 fma2(u64 a, u64 b, u64 c) {
    u64 r;
    asm("fma.rn.f32x2 %0, %1, %2, %3;" : "=l"(r) : "l"(a), "l"(b), "l"(c));
    return r;
}
__device__ __forceinline__ u64 pack2(float lo, float hi) {
    u64 r;
    asm("mov.b64 %0, {%1, %2};" : "=l"(r) : "f"(lo), "f"(hi));
    return r;
}
__device__ __forceinline__ void unpack2(u64 v, float& lo, float& hi) {
    asm("mov.b64 {%0, %1}, %2;" : "=f"(lo), "=f"(hi) : "l"(v));
}

__device__ __forceinline__ float gmm_scalar_one(const float* __restrict__ samples,
                                                long n) {
    float d[DM];
    for (int j = 0; j < DM; j++) d[j] = samples[n * DM + j];
    float pdf = 0.0f;
    for (int k = 0; k < KM; k++) {
        float quad = 0.0f;
        for (int i = 0; i < DM; i++) {
            float z = -g_v[k][i];
            for (int j = 0; j <= i; j++) z = fmaf(g_M[k][i][j], d[j], z);
            quad = fmaf(z, z, quad);
        }
        pdf += g_c[k] * __expf(-0.5f * quad);
    }
    return -logf(pdf);
}

__global__ __launch_bounds__(256, 4)
void gmm_main(const float4* __restrict__ samples4,
              const float* __restrict__ samples,
              float* __restrict__ out, int N) {
    __shared__ u64   sM2[KM][DM][DM];   // packed (m, m); zeros above diag. 32 KB
    __shared__ u64   svn2[KM][DM];      // packed (-v, -v)                   2 KB
    __shared__ float sc[KM];

    const float* gM = &g_M[0][0][0];
    for (int idx = threadIdx.x; idx < KM * DM * DM; idx += 256) {
        float m = gM[idx];
        ((u64*)sM2)[idx] = pack2(m, m);
    }
    const float* gv = &g_v[0][0];
    for (int idx = threadIdx.x; idx < KM * DM; idx += 256) {
        float v = gv[idx];
        ((u64*)svn2)[idx] = pack2(-v, -v);
    }
    if (threadIdx.x < KM) sc[threadIdx.x] = g_c[threadIdx.x];
    __syncthreads();

    long t = (long)blockIdx.x * blockDim.x + threadIdx.x;
    long base = t * 2;
    if (base >= N) return;

    if (base + 2 <= N) {
        // 2 samples packed lane-wise into f32x2.
        u64 d2[DM];
        {
            float r0[DM], r1[DM];
            #pragma unroll
            for (int q = 0; q < 4; q++) {
                float4 a = samples4[base * 4 + q];
                r0[4*q+0] = a.x; r0[4*q+1] = a.y; r0[4*q+2] = a.z; r0[4*q+3] = a.w;
                float4 b = samples4[(base + 1) * 4 + q];
                r1[4*q+0] = b.x; r1[4*q+1] = b.y; r1[4*q+2] = b.z; r1[4*q+3] = b.w;
            }
            #pragma unroll
            for (int j = 0; j < DM; j++) d2[j] = pack2(r0[j], r1[j]);
        }

        float pdf0 = 0.0f, pdf1 = 0.0f;

        #pragma unroll 1
        for (int k = 0; k < KM; k++) {
            u64 quadA = 0ull;
            #pragma unroll
            for (int i = 0; i < DM; i++) {
                u64 zA = svn2[k][i];
                // Row length padded to even; above-diagonal entry is 0 so the
                // extra FMA is a no-op. LDS.128 loads of (m,m) pairs.
                const int rlen = (i & 1) ? (i + 1) : (i + 2);
                #pragma unroll
                for (int j = 0; j < rlen; j += 2) {
                    ulonglong2 m2 = *(const ulonglong2*)&sM2[k][i][j];
                    zA = fma2(m2.x, d2[j],     zA);
                    zA = fma2(m2.y, d2[j + 1], zA);
                }
                quadA = fma2(zA, zA, quadA);
            }
            float q0, q1;
            unpack2(quadA, q0, q1);
            float c = sc[k];
            pdf0 += c * __expf(-0.5f * q0);
            pdf1 += c * __expf(-0.5f * q1);
        }
        out[base + 0] = -__logf(pdf0);
        out[base + 1] = -__logf(pdf1);
    } else {
        for (long n = base; n < N; n++)
            out[n] = gmm_scalar_one(samples, n);
    }
}

// ---------------------------------------------------------------------------
extern "C" void kernel_launch(void* const* d_in, const int* in_sizes, int n_in,
                              void* d_out, int out_size) {
    const float* samples = (const float*)d_in[0];
    const float* Phi     = (const float*)d_in[1];
    const float* mu      = (const float*)d_in[2];
    const float* Sigma   = (const float*)d_in[3];
    int N = in_sizes[0] / DM;

    gmm_precompute<<<1, 512>>>(Phi, mu, Sigma);

    int threads = (N + 1) / 2;
    int blocks  = (threads + 255) / 256;
    gmm_main<<<blocks, 256>>>((const float4*)samples, samples, (float*)d_out, N);
}

// round 4
// speedup vs baseline: 1.2045x; 1.2045x over previous
#include <cuda_runtime.h>
#include <math.h>

#define KM 16
#define DM 16

__device__ float g_M[KM][DM][DM];   // M = L^{-1}, lower triangular (zeros above diag)
__device__ float g_v[KM][DM];       // v = M @ mu
__device__ float g_c[KM];           // Phi / sqrt(2*pi*det(Sigma))

// ---------------------------------------------------------------------------
// Precompute: 1 block x 512 threads = 16 warps, one warp per mixture.
// ---------------------------------------------------------------------------
__global__ void gmm_precompute(const float* __restrict__ Phi,
                               const float* __restrict__ mu,
                               const float* __restrict__ Sigma) {
    __shared__ float L[KM][DM][DM + 1];
    __shared__ float Mi[KM][DM][DM + 1];

    int k    = threadIdx.x >> 5;
    int lane = threadIdx.x & 31;
    int r    = lane & 15;
    bool act = lane < 16;

    if (act)
        for (int j = 0; j < DM; j++)
            L[k][r][j] = Sigma[(k * DM + r) * DM + j];
    __syncwarp();

    for (int p = 0; p < DM; p++) {
        if (act && r == p) {
            float s = L[k][p][p];
            for (int q = 0; q < p; q++) s -= L[k][p][q] * L[k][p][q];
            L[k][p][p] = sqrtf(s);
        }
        __syncwarp();
        if (act && r > p) {
            float s = L[k][r][p];
            for (int q = 0; q < p; q++) s -= L[k][r][q] * L[k][p][q];
            L[k][r][p] = s / L[k][p][p];
        }
        __syncwarp();
    }

    if (act) {
        int c = r;
        for (int i = 0; i < c; i++) Mi[k][i][c] = 0.0f;
        Mi[k][c][c] = 1.0f / L[k][c][c];
        for (int i = c + 1; i < DM; i++) {
            float s = 0.0f;
            for (int q = c; q < i; q++) s += L[k][i][q] * Mi[k][q][c];
            Mi[k][i][c] = -s / L[k][i][i];
        }
    }
    __syncwarp();

    if (act) {
        float v = 0.0f;
        for (int j = 0; j <= r; j++) v += Mi[k][r][j] * mu[k * DM + j];
        g_v[k][r] = v;
        for (int j = 0; j < DM; j++) g_M[k][r][j] = Mi[k][r][j];
        if (r == 0) {
            float prod = 1.0f;
            for (int i = 0; i < DM; i++) prod *= L[k][i][i];
            g_c[k] = Phi[k] / (sqrtf(2.0f * 3.14159265358979323846f) * prod);
        }
    }
}

// ---------------------------------------------------------------------------
// Main kernel: 8 samples/thread = 4 packed f32x2 streams.
// One block/SM; per-warp ILP saturates the FMA pipe instead of occupancy.
// ---------------------------------------------------------------------------
typedef unsigned long long u64;

__device__ __forceinline__ u64 fma2(u64 a, u64 b, u64 c) {
    u64 r;
    asm("fma.rn.f32x2 %0, %1, %2, %3;" : "=l"(r) : "l"(a), "l"(b), "l"(c));
    return r;
}
__device__ __forceinline__ u64 pack2(float lo, float hi) {
    u64 r;
    asm("mov.b64 %0, {%1, %2};" : "=l"(r) : "f"(lo), "f"(hi));
    return r;
}
__device__ __forceinline__ void unpack2(u64 v, float& lo, float& hi) {
    asm("mov.b64 {%0, %1}, %2;" : "=f"(lo), "=f"(hi) : "l"(v));
}

__device__ __forceinline__ float gmm_scalar_one(const float* __restrict__ samples,
                                                long n) {
    float d[DM];
    for (int j = 0; j < DM; j++) d[j] = samples[n * DM + j];
    float pdf = 0.0f;
    for (int k = 0; k < KM; k++) {
        float quad = 0.0f;
        for (int i = 0; i < DM; i++) {
            float z = -g_v[k][i];
            for (int j = 0; j <= i; j++) z = fmaf(g_M[k][i][j], d[j], z);
            quad = fmaf(z, z, quad);
        }
        pdf += g_c[k] * __expf(-0.5f * quad);
    }
    return -logf(pdf);
}

#define NP 4   // packed pairs per thread (8 samples)

__global__ __launch_bounds__(256, 1)
void gmm_main(const float4* __restrict__ samples4,
              const float* __restrict__ samples,
              float* __restrict__ out, int N) {
    __shared__ u64   sM2[KM][DM][DM];   // packed (m, m); zeros above diag. 32 KB
    __shared__ u64   svn2[KM][DM];      // packed (-v, -v)                   2 KB
    __shared__ float sc[KM];

    const float* gM = &g_M[0][0][0];
    for (int idx = threadIdx.x; idx < KM * DM * DM; idx += 256) {
        float m = gM[idx];
        ((u64*)sM2)[idx] = pack2(m, m);
    }
    const float* gv = &g_v[0][0];
    for (int idx = threadIdx.x; idx < KM * DM; idx += 256) {
        float v = gv[idx];
        ((u64*)svn2)[idx] = pack2(-v, -v);
    }
    if (threadIdx.x < KM) sc[threadIdx.x] = g_c[threadIdx.x];
    __syncthreads();

    long t = (long)blockIdx.x * blockDim.x + threadIdx.x;
    long base = t * (2 * NP);
    if (base >= N) return;

    if (base + 2 * NP <= N) {
        u64 d2[NP][DM];
        #pragma unroll
        for (int p = 0; p < NP; p++) {
            float r0[DM], r1[DM];
            #pragma unroll
            for (int q = 0; q < 4; q++) {
                float4 a = samples4[(base + 2 * p) * 4 + q];
                r0[4*q+0] = a.x; r0[4*q+1] = a.y; r0[4*q+2] = a.z; r0[4*q+3] = a.w;
                float4 b = samples4[(base + 2 * p + 1) * 4 + q];
                r1[4*q+0] = b.x; r1[4*q+1] = b.y; r1[4*q+2] = b.z; r1[4*q+3] = b.w;
            }
            #pragma unroll
            for (int j = 0; j < DM; j++) d2[p][j] = pack2(r0[j], r1[j]);
        }

        float pdf[2 * NP];
        #pragma unroll
        for (int s = 0; s < 2 * NP; s++) pdf[s] = 0.0f;

        #pragma unroll 1
        for (int k = 0; k < KM; k++) {
            u64 q2[NP];
            #pragma unroll
            for (int p = 0; p < NP; p++) q2[p] = 0ull;

            #pragma unroll
            for (int i = 0; i < DM; i++) {
                u64 z[NP];
                u64 v0 = svn2[k][i];
                #pragma unroll
                for (int p = 0; p < NP; p++) z[p] = v0;
                // Row padded to even length; above-diagonal entry is 0.
                const int rlen = (i & 1) ? (i + 1) : (i + 2);
                #pragma unroll
                for (int j = 0; j < rlen; j += 2) {
                    ulonglong2 m2 = *(const ulonglong2*)&sM2[k][i][j];
                    #pragma unroll
                    for (int p = 0; p < NP; p++) {
                        z[p] = fma2(m2.x, d2[p][j],     z[p]);
                        z[p] = fma2(m2.y, d2[p][j + 1], z[p]);
                    }
                }
                #pragma unroll
                for (int p = 0; p < NP; p++) q2[p] = fma2(z[p], z[p], q2[p]);
            }

            float c = sc[k];
            #pragma unroll
            for (int p = 0; p < NP; p++) {
                float qa, qb;
                unpack2(q2[p], qa, qb);
                pdf[2*p + 0] += c * __expf(-0.5f * qa);
                pdf[2*p + 1] += c * __expf(-0.5f * qb);
            }
        }

        #pragma unroll
        for (int p = 0; p < NP; p++) {
            out[base + 2*p + 0] = -__logf(pdf[2*p + 0]);
            out[base + 2*p + 1] = -__logf(pdf[2*p + 1]);
        }
    } else {
        for (long n = base; n < N; n++)
            out[n] = gmm_scalar_one(samples, n);
    }
}

// ---------------------------------------------------------------------------
extern "C" void kernel_launch(void* const* d_in, const int* in_sizes, int n_in,
                              void* d_out, int out_size) {
    const float* samples = (const float*)d_in[0];
    const float* Phi     = (const float*)d_in[1];
    const float* mu      = (const float*)d_in[2];
    const float* Sigma   = (const float*)d_in[3];
    int N = in_sizes[0] / DM;

    gmm_precompute<<<1, 512>>>(Phi, mu, Sigma);

    int threads = (N + 2 * NP - 1) / (2 * NP);
    int blocks  = (threads + 255) / 256;
    gmm_main<<<blocks, 256>>>((const float4*)samples, samples, (float*)d_out, N);
}